// round 15
// baseline (speedup 1.0000x reference)
#include <cuda_runtime.h>
#include <cuda_fp16.h>
#include <cstdint>
#include <math.h>

// ---------------- problem constants ----------------
#define Hd   4096
#define Id   14336
#define Rr   159
#define R2   318
#define Ee   8
#define Tt   4096
#define RT   8192          // total routed rows (Tt * topk)

#define STAGES  3
#define TILE_B  16384      // one 128x64 fp16 tile
#define QNC2    224        // 14336 / 64 (full K)

// ---------------- scratch (device globals) ----------------
__device__ int   g_cnt[Ee];
__device__ int   g_off[Ee];
__device__ int   g_tok[Ee][Tt];
__device__ float g_wt[Ee][Tt];

__device__ __align__(16) __half g_xh[(size_t)Tt * Hd];
__device__ __align__(16) __half g_Bp[(size_t)Ee * 640 * Hd];      // rows: 0-317 gate(w1v,v1), 320-637 up(w3v,v3)
__device__ __align__(16) __half g_Bg[(size_t)Ee * Id * 320];      // [I,320] = w1u|u1|pad
__device__ __align__(16) __half g_Bu[(size_t)Ee * Id * 320];      // w3u|u3|pad
__device__ __align__(16) __half g_Bq[(size_t)Ee * 384 * Id];      // rows: w2v|v2 (only 320 used)
__device__ __align__(16) __half g_Bo[(size_t)Ee * Hd * 320];      // w2u|u2|pad
__device__ __align__(16) __half g_Ph[(size_t)RT * 640];           // hi only (A of gate/up)
__device__ __align__(16) __half g_hh[(size_t)RT * Id];            // hi only (A of Q)
__device__ __align__(16) __half g_Qh[(size_t)RT * 320];

// ---------------- PTX helpers ----------------
__device__ __forceinline__ uint32_t smem_to_u32(const void* p) {
    uint32_t a;
    asm("{ .reg .u64 t; cvta.to.shared.u64 t, %1; cvt.u32.u64 %0, t; }" : "=r"(a) : "l"(p));
    return a;
}
#define LDSM4(r, a)                                                               \
    asm volatile("ldmatrix.sync.aligned.m8n8.x4.shared.b16 {%0,%1,%2,%3}, [%4];"  \
        : "=r"((r)[0]), "=r"((r)[1]), "=r"((r)[2]), "=r"((r)[3]) : "r"(a))
#define LDSM2(r, a)                                                               \
    asm volatile("ldmatrix.sync.aligned.m8n8.x2.shared.b16 {%0,%1}, [%2];"        \
        : "=r"((r)[0]), "=r"((r)[1]) : "r"(a))
#define MMA16816(d, a, b)                                                         \
    asm volatile("mma.sync.aligned.m16n8k16.row.col.f32.f16.f16.f32 "             \
        "{%0,%1,%2,%3},{%4,%5,%6,%7},{%8,%9},{%0,%1,%2,%3};"                      \
        : "+f"((d)[0]), "+f"((d)[1]), "+f"((d)[2]), "+f"((d)[3])                  \
        : "r"((a)[0]), "r"((a)[1]), "r"((a)[2]), "r"((a)[3]),                     \
          "r"((b)[0]), "r"((b)[1]))
#define CP16(dst, src, sz)                                                        \
    asm volatile("cp.async.cg.shared.global [%0], [%1], 16, %2;"                  \
        :: "r"(dst), "l"(src), "r"(sz))
#define CP_COMMIT() asm volatile("cp.async.commit_group;" ::: "memory")
#define CP_WAIT(n)  asm volatile("cp.async.wait_group %0;" :: "n"(n) : "memory")

__device__ __forceinline__ uint32_t tile_off(int row, int chunk) {
    return (uint32_t)(row * 128 + ((chunk ^ (row & 7)) << 4));
}

// ---------------- conversion / packing kernels ----------------
__global__ __launch_bounds__(256) void k_conv_Bp(
    const float* __restrict__ w1v, const float* __restrict__ v1,
    const float* __restrict__ w3v, const float* __restrict__ v3)
{
    int j = blockIdx.x, e = blockIdx.y;
    const float* src = nullptr;
    if      (j < Rr)            src = w1v + ((size_t)e * Rr + j) * Hd;
    else if (j < R2)            src = v1  + ((size_t)e * Rr + j - Rr) * Hd;
    else if (j >= 320 && j < 320 + Rr) src = w3v + ((size_t)e * Rr + j - 320) * Hd;
    else if (j >= 320 + Rr && j < 320 + R2) src = v3 + ((size_t)e * Rr + j - 320 - Rr) * Hd;
    __half2* dst = (__half2*)(g_Bp + ((size_t)e * 640 + j) * Hd);
    for (int i = threadIdx.x; i < Hd / 2; i += 256) {
        float2 v = src ? ((const float2*)src)[i] : make_float2(0.f, 0.f);
        dst[i] = __floats2half2_rn(v.x, v.y);
    }
}

template <int SEL>  // 0: Bg(w1u,u1,I)  1: Bu(w3u,u3,I)  2: Bo(w2u,u2,H)
__global__ __launch_bounds__(320) void k_pack320(
    const float* __restrict__ W, const float* __restrict__ U)
{
    constexpr int ROWS = (SEL == 2) ? Hd : Id;
    __half* D = (SEL == 0) ? g_Bg : (SEL == 1) ? g_Bu : g_Bo;
    int e = blockIdx.y;
    int r = blockIdx.x * 4 + (threadIdx.x / 80);
    int c4 = (threadIdx.x % 80) * 4;
    const float* w = W + ((size_t)e * ROWS + r) * Rr;
    const float* u = U + ((size_t)e * ROWS + r) * Rr;
    float v[4];
#pragma unroll
    for (int j = 0; j < 4; j++) {
        int k = c4 + j;
        v[j] = (k < Rr) ? w[k] : ((k < R2) ? u[k - Rr] : 0.f);
    }
    __half2 h0 = __floats2half2_rn(v[0], v[1]);
    __half2 h1 = __floats2half2_rn(v[2], v[3]);
    uint2 pk = make_uint2(*(uint32_t*)&h0, *(uint32_t*)&h1);
    *(uint2*)(D + ((size_t)e * ROWS + r) * 320 + c4) = pk;
}

__global__ __launch_bounds__(256) void k_conv_Bq(
    const float* __restrict__ w2v, const float* __restrict__ v2)
{
    int j = blockIdx.x, e = blockIdx.y;   // j in [0,320)
    const float* src = nullptr;
    if      (j < Rr) src = w2v + ((size_t)e * Rr + j) * Id;
    else if (j < R2) src = v2  + ((size_t)e * Rr + j - Rr) * Id;
    __half2* dst = (__half2*)(g_Bq + ((size_t)e * 384 + j) * Id);
    for (int i = threadIdx.x; i < Id / 2; i += 256) {
        float2 v = src ? ((const float2*)src)[i] : make_float2(0.f, 0.f);
        dst[i] = __floats2half2_rn(v.x, v.y);
    }
}

// ---------------- router (fused: logits fp32 + x -> fp16), 16 tokens/CTA ----------------
__device__ __forceinline__ float warpsum(float v) {
#pragma unroll
    for (int o = 16; o; o >>= 1) v += __shfl_down_sync(0xffffffffu, v, o);
    return v;
}

__global__ __launch_bounds__(256) void router_kernel(
    const float* __restrict__ x, const float* __restrict__ gw, float* __restrict__ logits)
{
    extern __shared__ float sgw[];   // [Ee * Hd] = 128KB
    int tid = threadIdx.x;
    for (int i = tid; i < Ee * Hd / 4; i += 256)
        ((float4*)sgw)[i] = ((const float4*)gw)[i];
    __syncthreads();

    int lane = tid & 31, grp = tid >> 5;
#pragma unroll
    for (int tt = 0; tt < 2; tt++) {
        int t = blockIdx.x * 16 + grp * 2 + tt;
        const float4* xr = (const float4*)(x + (size_t)t * Hd);
        __half2* dh = (__half2*)(g_xh + (size_t)t * Hd);

        float acc[Ee];
#pragma unroll
        for (int e = 0; e < Ee; e++) acc[e] = 0.f;

        for (int it = 0; it < Hd / 4 / 32; it++) {
            int i = lane + it * 32;
            float4 xv = xr[i];
            dh[2 * i]     = __floats2half2_rn(xv.x, xv.y);
            dh[2 * i + 1] = __floats2half2_rn(xv.z, xv.w);
#pragma unroll
            for (int e = 0; e < Ee; e++) {
                float4 wv = ((const float4*)(sgw + (size_t)e * Hd))[i];
                acc[e] = fmaf(xv.x, wv.x, fmaf(xv.y, wv.y, fmaf(xv.z, wv.z, fmaf(xv.w, wv.w, acc[e]))));
            }
        }
#pragma unroll
        for (int e = 0; e < Ee; e++) {
            float s = warpsum(acc[e]);
            if (lane == 0) logits[(size_t)t * Ee + e] = s;
        }
    }
}

__global__ void prep_kernel() { if (threadIdx.x < Ee) g_cnt[threadIdx.x] = 0; }

__global__ void route_kernel(const float* __restrict__ logits)
{
    int t = blockIdx.x * blockDim.x + threadIdx.x;
    if (t >= Tt) return;
    float l[Ee];
#pragma unroll
    for (int e = 0; e < Ee; e++) l[e] = logits[(size_t)t * Ee + e];
    int i1 = 0; float m1 = l[0];
#pragma unroll
    for (int e = 1; e < Ee; e++) if (l[e] > m1) { m1 = l[e]; i1 = e; }
    int i2 = -1; float m2 = -1e30f;
#pragma unroll
    for (int e = 0; e < Ee; e++) if (e != i1 && l[e] > m2) { m2 = l[e]; i2 = e; }
    float w1 = 1.f / (1.f + expf(m2 - m1));
    float w2 = 1.f - w1;
    int p = atomicAdd(&g_cnt[i1], 1); g_tok[i1][p] = t; g_wt[i1][p] = w1;
    p     = atomicAdd(&g_cnt[i2], 1); g_tok[i2][p] = t; g_wt[i2][p] = w2;
}

__global__ void offsets_kernel()
{
    if (threadIdx.x == 0) {
        int s = 0;
        for (int e = 0; e < Ee; e++) { g_off[e] = s; s += g_cnt[e]; }
    }
}

// ---------------- fp16 HMMA GEMM (128-M tile family, single-A), expert-pair ----------------
// KIND 0: P = gather(xh) @ Bp^T       K=4096 NC=64  N=640(5)    3-stage
// KIND 1: h = silu(P@Bg^T)*(P@Bu^T)   fused NC=10 (gate 0-4, up 5-9), 2-stage + stash
// KIND 3: out += wt * (Q @ Bo^T)      K=320 NC=5    N=4096(32)  3-stage
template <int KIND>
__global__ __launch_bounds__(256, 2) void moe_mma(float* __restrict__ outp, int ebase)
{
    constexpr int NSTAGE = (KIND == 1) ? 2 : STAGES;
    constexpr int STAGE_B = 2 * TILE_B;
    constexpr int NCc   = (KIND == 0) ? 64 : (KIND == 1) ? 10 : 5;
    constexpr int Kb    = (KIND == 0) ? Hd : 320;
    constexpr int Brows = (KIND == 0) ? 640 : (KIND == 1) ? Id : Hd;

    int e     = ebase + blockIdx.z;
    int n_e   = g_cnt[e];
    int mbase = blockIdx.x * 128;
    if (mbase >= n_e) return;
    int nbase = blockIdx.y * 128;
    int off   = g_off[e];

    extern __shared__ char smem[];
    uint32_t smem_u32 = smem_to_u32(smem);
    __half2* sg2 = (__half2*)(smem + NSTAGE * STAGE_B);   // KIND1 silu stash (32KB, per-thread)

    int tid = threadIdx.x, lane = tid & 31, wid = tid >> 5;
    int wm = wid & 1, wn = wid >> 1;
    int row = tid >> 1, half = tid & 1;
    int ml = mbase + row;
    unsigned szA = (ml < n_e) ? 16u : 0u;

    const __half* Ah_row;
    if (KIND == 0) {
        int t = (ml < n_e) ? g_tok[e][ml] : 0;
        Ah_row = g_xh + (size_t)t * Hd;
    } else {
        size_t r = (size_t)off + ((ml < n_e) ? ml : 0);
        Ah_row = (KIND == 1) ? (g_Ph + r * 640) : (g_Qh + r * 320);
    }

    const __half *BrowG = nullptr, *BrowU = nullptr, *Brow = nullptr;
    if (KIND == 1) {
        size_t ro = ((size_t)e * Brows + nbase + row) * 320;
        BrowG = g_Bg + ro;
        BrowU = g_Bu + ro;
    } else {
        const __half* Bm = (KIND == 0) ? g_Bp : g_Bo;
        Brow = Bm + ((size_t)e * Brows + nbase + row) * Kb;
    }

    float acc[4][4][4];
#pragma unroll
    for (int i = 0; i < 4; i++)
#pragma unroll
        for (int j = 0; j < 4; j++)
#pragma unroll
            for (int q = 0; q < 4; q++) acc[i][j][q] = 0.f;

    auto issue_load = [&](int st, int c) {
        uint32_t sb = smem_u32 + st * STAGE_B;
        int acol = c * 64 + half * 32;
        const __half* bsrc;
        int bcol;
        if (KIND == 1) {
            bsrc = (c < 5) ? BrowG : BrowU;
            bcol = (c % 5) * 64 + half * 32;
        } else {
            bsrc = Brow;
            bcol = acol;
        }
#pragma unroll
        for (int i = 0; i < 4; i++) {
            uint32_t so = tile_off(row, half * 4 + i);
            CP16(sb + so, Ah_row + acol + i * 8, szA);
            CP16(sb + TILE_B + so, bsrc + bcol + i * 8, 16u);
        }
    };

    auto compute = [&](int st) {
        uint32_t base = smem_u32 + st * STAGE_B;
#pragma unroll
        for (int ks = 0; ks < 4; ks++) {
            uint32_t Ahf[4][4], Bf[4][2];
#pragma unroll
            for (int mf = 0; mf < 4; mf++) {
                int ar = wm * 64 + mf * 16 + (lane & 15);
                LDSM4(Ahf[mf], base + tile_off(ar, ks * 2 + (lane >> 4)));
            }
#pragma unroll
            for (int g = 0; g < 2; g++) {
                int br = wn * 32 + g * 16 + ((lane >> 4) << 3) + (lane & 7);
                uint32_t o = tile_off(br, ks * 2 + ((lane >> 3) & 1));
                uint32_t r[4];
                LDSM4(r, base + TILE_B + o);
                Bf[2 * g][0] = r[0]; Bf[2 * g][1] = r[1];
                Bf[2 * g + 1][0] = r[2]; Bf[2 * g + 1][1] = r[3];
            }
#pragma unroll
            for (int mf = 0; mf < 4; mf++)
#pragma unroll
                for (int nf = 0; nf < 4; nf++) MMA16816(acc[mf][nf], Ahf[mf], Bf[nf]);
        }
    };

    auto stash_silu = [&]() {
#pragma unroll
        for (int mf = 0; mf < 4; mf++)
#pragma unroll
            for (int nf = 0; nf < 4; nf++)
#pragma unroll
                for (int qp = 0; qp < 2; qp++) {
                    float g0 = acc[mf][nf][qp * 2 + 0];
                    float g1 = acc[mf][nf][qp * 2 + 1];
                    g0 = g0 / (1.f + __expf(-g0));
                    g1 = g1 / (1.f + __expf(-g1));
                    sg2[((mf * 4 + nf) * 2 + qp) * 256 + tid] = __floats2half2_rn(g0, g1);
                    acc[mf][nf][qp * 2 + 0] = 0.f;
                    acc[mf][nf][qp * 2 + 1] = 0.f;
                }
    };

    if (NSTAGE == 3) {
        issue_load(0, 0); CP_COMMIT();
        if (NCc > 1) issue_load(1, 1);
        CP_COMMIT();
        CP_WAIT(1);
        __syncthreads();
        for (int c = 0; c < NCc; c++) {
            if (c + 2 < NCc) issue_load((c + 2) % 3, c + 2);
            CP_COMMIT();
            compute(c % 3);
            CP_WAIT(1);
            __syncthreads();
        }
    } else {
        issue_load(0, 0); CP_COMMIT();
        CP_WAIT(0);
        __syncthreads();
        for (int c = 0; c < NCc; c++) {
            if (c + 1 < NCc) { issue_load((c + 1) & 1, c + 1); CP_COMMIT(); }
            compute(c & 1);
            if (KIND == 1 && c == 4) stash_silu();   // per-thread smem, no sync needed
            if (c + 1 < NCc) { CP_WAIT(0); __syncthreads(); }
        }
    }

    // epilogue
#pragma unroll
    for (int mf = 0; mf < 4; mf++)
#pragma unroll
        for (int nf = 0; nf < 4; nf++)
#pragma unroll
            for (int qp = 0; qp < 2; qp++) {
                int r = wm * 64 + mf * 16 + (lane >> 2) + qp * 8;
                int m = mbase + r;
                if (m >= n_e) continue;
                int col = nbase + wn * 32 + nf * 8 + (lane & 3) * 2;
                float v0 = acc[mf][nf][qp * 2 + 0];
                float v1 = acc[mf][nf][qp * 2 + 1];
                if (KIND == 0) {
                    size_t b = (size_t)(off + m) * 640 + col;
                    *(__half2*)(g_Ph + b) = __floats2half2_rn(v0, v1);
                } else if (KIND == 1) {
                    float2 sf = __half22float2(sg2[((mf * 4 + nf) * 2 + qp) * 256 + tid]);
                    v0 *= sf.x;
                    v1 *= sf.y;
                    size_t b = (size_t)(off + m) * Id + col;
                    *(__half2*)(g_hh + b) = __floats2half2_rn(v0, v1);
                } else {
                    float wt  = g_wt[e][m];
                    int   tok = g_tok[e][m];
                    float* dst = outp + (size_t)tok * Hd + col;
                    atomicAdd(dst, wt * v0);
                    atomicAdd(dst + 1, wt * v1);
                }
            }
}

// ---------------- Q GEMM: M=64 x N=160, FULL K=14336, 3-stage, 2 CTAs/SM ----------------
// Writes g_Qh (fp16) directly — no K-split, no qsum.
#define QA_B 8192
#define QB_B 20480
#define QST_B (QA_B + QB_B)   // 28672
__global__ __launch_bounds__(256, 2) void moe_mma_q(int ebase)
{
    int e     = ebase + blockIdx.z;
    int n_e   = g_cnt[e];
    int mbase = blockIdx.x * 64;
    if (mbase >= n_e) return;
    int nhalf = blockIdx.y;
    int off   = g_off[e];

    extern __shared__ char smem[];
    uint32_t smem_u32 = smem_to_u32(smem);

    int tid = threadIdx.x, lane = tid & 31, wid = tid >> 5;
    int wm = wid >> 2, wn = wid & 3;   // 2M x 4N warps

    float acc[2][5][4];
#pragma unroll
    for (int i = 0; i < 2; i++)
#pragma unroll
        for (int j = 0; j < 5; j++)
#pragma unroll
            for (int q = 0; q < 4; q++) acc[i][j][q] = 0.f;

    const __half* Bq_e = g_Bq + (size_t)e * 384 * Id + (size_t)(nhalf * 160) * Id;

    auto issue_load = [&](int st, int c) {
        uint32_t sb = smem_u32 + st * QST_B;
        int col = c * 64;
#pragma unroll
        for (int i = 0; i < 7; i++) {
            int ci = tid + i * 256;
            if (ci < 512) {
                int row = ci >> 3, ch = ci & 7;
                int m = mbase + row;
                unsigned sz = (m < n_e) ? 16u : 0u;
                const __half* src = g_hh + ((size_t)off + ((m < n_e) ? m : 0)) * Id + col + ch * 8;
                CP16(sb + tile_off(row, ch), src, sz);
            } else {
                int bi = ci - 512;   // < 1280
                int row = bi >> 3, ch = bi & 7;
                const __half* src = Bq_e + (size_t)row * Id + col + ch * 8;
                CP16(sb + QA_B + tile_off(row, ch), src, 16u);
            }
        }
    };

    auto compute = [&](int st) {
        uint32_t base = smem_u32 + st * QST_B;
#pragma unroll
        for (int ks = 0; ks < 4; ks++) {
            uint32_t Af[2][4], Bf[5][2];
#pragma unroll
            for (int mf = 0; mf < 2; mf++) {
                int ar = wm * 32 + mf * 16 + (lane & 15);
                LDSM4(Af[mf], base + tile_off(ar, ks * 2 + (lane >> 4)));
            }
#pragma unroll
            for (int g = 0; g < 2; g++) {
                int br = wn * 40 + g * 16 + ((lane >> 4) << 3) + (lane & 7);
                uint32_t o = tile_off(br, ks * 2 + ((lane >> 3) & 1));
                uint32_t r[4];
                LDSM4(r, base + QA_B + o);
                Bf[2 * g][0] = r[0]; Bf[2 * g][1] = r[1];
                Bf[2 * g + 1][0] = r[2]; Bf[2 * g + 1][1] = r[3];
            }
            {
                int br = wn * 40 + 32 + (lane & 7);
                uint32_t o = tile_off(br, ks * 2 + ((lane >> 3) & 1));
                uint32_t r2[2];
                LDSM2(r2, base + QA_B + o);
                Bf[4][0] = r2[0]; Bf[4][1] = r2[1];
            }
#pragma unroll
            for (int mf = 0; mf < 2; mf++)
#pragma unroll
                for (int nf = 0; nf < 5; nf++) MMA16816(acc[mf][nf], Af[mf], Bf[nf]);
        }
    };

    issue_load(0, 0); CP_COMMIT();
    issue_load(1, 1); CP_COMMIT();
    CP_WAIT(1);
    __syncthreads();

    for (int c = 0; c < QNC2; c++) {
        if (c + 2 < QNC2) issue_load((c + 2) % 3, c + 2);
        CP_COMMIT();
        compute(c % 3);
        CP_WAIT(1);
        __syncthreads();
    }

#pragma unroll
    for (int mf = 0; mf < 2; mf++)
#pragma unroll
        for (int nf = 0; nf < 5; nf++)
#pragma unroll
            for (int qp = 0; qp < 2; qp++) {
                int m = mbase + wm * 32 + mf * 16 + (lane >> 2) + qp * 8;
                if (m >= n_e) continue;
                int col = nhalf * 160 + wn * 40 + nf * 8 + (lane & 3) * 2;
                size_t b = (size_t)(off + m) * 320 + col;
                *(__half2*)(g_Qh + b) =
                    __floats2half2_rn(acc[mf][nf][qp * 2 + 0], acc[mf][nf][qp * 2 + 1]);
            }
}

// ---------------- launch ----------------
extern "C" void kernel_launch(void* const* d_in, const int* in_sizes, int n_in,
                              void* d_out, int out_size)
{
    const float* x    = (const float*)d_in[0];
    const float* gw   = (const float*)d_in[1];
    const float* w1u  = (const float*)d_in[2];
    const float* w1v  = (const float*)d_in[3];
    const float* w2u  = (const float*)d_in[4];
    const float* w2v  = (const float*)d_in[5];
    const float* w3u  = (const float*)d_in[6];
    const float* w3v  = (const float*)d_in[7];
    const float* u1   = (const float*)d_in[8];
    const float* v1   = (const float*)d_in[9];
    const float* u2   = (const float*)d_in[10];
    const float* v2   = (const float*)d_in[11];
    const float* u3   = (const float*)d_in[12];
    const float* v3   = (const float*)d_in[13];

    float* outp   = (float*)d_out;
    float* logits = outp + (size_t)Tt * Hd;

    static cudaStream_t s_pack = nullptr;
    static cudaEvent_t evStart, evBp, evBgu, evBq, evBo, evRoute, evZero, evDoneB;
    if (!s_pack) {
        cudaStreamCreateWithFlags(&s_pack, cudaStreamNonBlocking);
        cudaEventCreateWithFlags(&evStart, cudaEventDisableTiming);
        cudaEventCreateWithFlags(&evBp,    cudaEventDisableTiming);
        cudaEventCreateWithFlags(&evBgu,   cudaEventDisableTiming);
        cudaEventCreateWithFlags(&evBq,    cudaEventDisableTiming);
        cudaEventCreateWithFlags(&evBo,    cudaEventDisableTiming);
        cudaEventCreateWithFlags(&evRoute, cudaEventDisableTiming);
        cudaEventCreateWithFlags(&evZero,  cudaEventDisableTiming);
        cudaEventCreateWithFlags(&evDoneB, cudaEventDisableTiming);

        int smem_s2 = STAGES * 2 * TILE_B;        // 96KB (KIND0/3)
        int smem_gu = 2 * 2 * TILE_B + 32768;     // 96KB (KIND1)
        int smem_q  = 3 * QST_B;                  // 84KB
        cudaFuncSetAttribute(moe_mma<0>, cudaFuncAttributeMaxDynamicSharedMemorySize, smem_s2);
        cudaFuncSetAttribute(moe_mma<1>, cudaFuncAttributeMaxDynamicSharedMemorySize, smem_gu);
        cudaFuncSetAttribute(moe_mma<3>, cudaFuncAttributeMaxDynamicSharedMemorySize, smem_s2);
        cudaFuncSetAttribute(moe_mma_q,  cudaFuncAttributeMaxDynamicSharedMemorySize, smem_q);
        cudaFuncSetAttribute(router_kernel, cudaFuncAttributeMaxDynamicSharedMemorySize,
                             Ee * Hd * (int)sizeof(float));   // 128KB
    }
    int smem_s2 = STAGES * 2 * TILE_B;
    int smem_gu = 2 * 2 * TILE_B + 32768;
    int smem_q  = 3 * QST_B;

    // fork: weight packing on side stream
    cudaEventRecord(evStart, 0);
    cudaStreamWaitEvent(s_pack, evStart, 0);

    k_conv_Bp<<<dim3(640, Ee), 256, 0, s_pack>>>(w1v, v1, w3v, v3);
    cudaEventRecord(evBp, s_pack);
    k_pack320<0><<<dim3(Id / 4, Ee), 320, 0, s_pack>>>(w1u, u1);
    k_pack320<1><<<dim3(Id / 4, Ee), 320, 0, s_pack>>>(w3u, u3);
    cudaEventRecord(evBgu, s_pack);
    k_conv_Bq<<<dim3(320, Ee), 256, 0, s_pack>>>(w2v, v2);
    cudaEventRecord(evBq, s_pack);
    k_pack320<2><<<dim3(Hd / 4, Ee), 320, 0, s_pack>>>(w2u, u2);
    cudaEventRecord(evBo, s_pack);

    // main stream: routing chain (router also produces g_xh)
    cudaMemsetAsync(outp, 0, (size_t)Tt * Hd * sizeof(float));
    cudaEventRecord(evZero, 0);
    prep_kernel<<<1, 32>>>();
    router_kernel<<<Tt / 16, 256, Ee * Hd * sizeof(float)>>>(x, gw, logits);
    route_kernel<<<Tt / 256, 256>>>(logits);
    offsets_kernel<<<1, 32>>>();
    cudaEventRecord(evRoute, 0);

    // pair-chains: {0,1},{2,3} on main; {4,5},{6,7} on s_pack
    // chain A0 (experts 0,1) — main stream
    cudaStreamWaitEvent(0, evBp, 0);
    moe_mma<0><<<dim3(32, 5, 2), 256, smem_s2>>>(nullptr, 0);
    cudaStreamWaitEvent(0, evBgu, 0);
    moe_mma<1><<<dim3(32, 112, 2), 256, smem_gu>>>(nullptr, 0);
    cudaStreamWaitEvent(0, evBq, 0);
    moe_mma_q<<<dim3(64, 2, 2), 256, smem_q>>>(0);
    cudaStreamWaitEvent(0, evBo, 0);
    moe_mma<3><<<dim3(32, 32, 2), 256, smem_s2>>>(outp, 0);
    // chain A1 (experts 2,3) — main stream (pack events already honored above)
    moe_mma<0><<<dim3(32, 5, 2), 256, smem_s2>>>(nullptr, 2);
    moe_mma<1><<<dim3(32, 112, 2), 256, smem_gu>>>(nullptr, 2);
    moe_mma_q<<<dim3(64, 2, 2), 256, smem_q>>>(2);
    moe_mma<3><<<dim3(32, 32, 2), 256, smem_s2>>>(outp, 2);

    // chain B0 (experts 4,5) — s_pack (packing ordered earlier on this stream)
    cudaStreamWaitEvent(s_pack, evRoute, 0);
    cudaStreamWaitEvent(s_pack, evZero, 0);
    moe_mma<0><<<dim3(32, 5, 2), 256, smem_s2, s_pack>>>(nullptr, 4);
    moe_mma<1><<<dim3(32, 112, 2), 256, smem_gu, s_pack>>>(nullptr, 4);
    moe_mma_q<<<dim3(64, 2, 2), 256, smem_q, s_pack>>>(4);
    moe_mma<3><<<dim3(32, 32, 2), 256, smem_s2, s_pack>>>(outp, 4);
    // chain B1 (experts 6,7) — s_pack
    moe_mma<0><<<dim3(32, 5, 2), 256, smem_s2, s_pack>>>(nullptr, 6);
    moe_mma<1><<<dim3(32, 112, 2), 256, smem_gu, s_pack>>>(nullptr, 6);
    moe_mma_q<<<dim3(64, 2, 2), 256, smem_q, s_pack>>>(6);
    moe_mma<3><<<dim3(32, 32, 2), 256, smem_s2, s_pack>>>(outp, 6);
    cudaEventRecord(evDoneB, s_pack);

    // join
    cudaStreamWaitEvent(0, evDoneB, 0);
}

// round 16
// speedup vs baseline: 1.2667x; 1.2667x over previous
#include <cuda_runtime.h>
#include <cuda_fp16.h>
#include <cstdint>
#include <math.h>

// ---------------- problem constants ----------------
#define Hd   4096
#define Id   14336
#define Rr   159
#define R2   318
#define Ee   8
#define Tt   4096
#define RT   8192          // total routed rows (Tt * topk)

#define STAGES  3
#define TILE_B  16384      // one 128x64 fp16 tile
#define QSPLIT  4
#define QNC     56         // 14336 / 64 / 4

// ---------------- scratch (device globals) ----------------
__device__ int   g_cnt[Ee];
__device__ int   g_off[Ee];
__device__ int   g_tok[Ee][Tt];
__device__ float g_wt[Ee][Tt];

__device__ __align__(16) __half g_xh[(size_t)Tt * Hd];
__device__ __align__(16) __half g_Bp[(size_t)Ee * 640 * Hd];      // rows: 0-317 gate(w1v,v1), 320-637 up(w3v,v3)
__device__ __align__(16) __half g_Bg[(size_t)Ee * Id * 320];      // [I,320] = w1u|u1|pad
__device__ __align__(16) __half g_Bu[(size_t)Ee * Id * 320];      // w3u|u3|pad
__device__ __align__(16) __half g_Bq[(size_t)Ee * 384 * Id];      // rows: w2v|v2 (only 320 used)
__device__ __align__(16) __half g_Bo[(size_t)Ee * Hd * 320];      // w2u|u2|pad
__device__ __align__(16) __half g_Ph[(size_t)RT * 640];           // hi only (A of gate/up)
__device__ __align__(16) __half g_hh[(size_t)RT * Id];            // hi only (A of Q)
__device__ float g_Qf[(size_t)QSPLIT * RT * 320];
__device__ __align__(16) __half g_Qh[(size_t)RT * 320];

// ---------------- PTX helpers ----------------
__device__ __forceinline__ uint32_t smem_to_u32(const void* p) {
    uint32_t a;
    asm("{ .reg .u64 t; cvta.to.shared.u64 t, %1; cvt.u32.u64 %0, t; }" : "=r"(a) : "l"(p));
    return a;
}
#define LDSM4(r, a)                                                               \
    asm volatile("ldmatrix.sync.aligned.m8n8.x4.shared.b16 {%0,%1,%2,%3}, [%4];"  \
        : "=r"((r)[0]), "=r"((r)[1]), "=r"((r)[2]), "=r"((r)[3]) : "r"(a))
#define LDSM2(r, a)                                                               \
    asm volatile("ldmatrix.sync.aligned.m8n8.x2.shared.b16 {%0,%1}, [%2];"        \
        : "=r"((r)[0]), "=r"((r)[1]) : "r"(a))
#define MMA16816(d, a, b)                                                         \
    asm volatile("mma.sync.aligned.m16n8k16.row.col.f32.f16.f16.f32 "             \
        "{%0,%1,%2,%3},{%4,%5,%6,%7},{%8,%9},{%0,%1,%2,%3};"                      \
        : "+f"((d)[0]), "+f"((d)[1]), "+f"((d)[2]), "+f"((d)[3])                  \
        : "r"((a)[0]), "r"((a)[1]), "r"((a)[2]), "r"((a)[3]),                     \
          "r"((b)[0]), "r"((b)[1]))
#define CP16(dst, src, sz)                                                        \
    asm volatile("cp.async.cg.shared.global [%0], [%1], 16, %2;"                  \
        :: "r"(dst), "l"(src), "r"(sz))
#define CP_COMMIT() asm volatile("cp.async.commit_group;" ::: "memory")
#define CP_WAIT(n)  asm volatile("cp.async.wait_group %0;" :: "n"(n) : "memory")

__device__ __forceinline__ uint32_t tile_off(int row, int chunk) {
    return (uint32_t)(row * 128 + ((chunk ^ (row & 7)) << 4));
}

// ---------------- conversion / packing kernels ----------------
__global__ __launch_bounds__(256) void k_conv_Bp(
    const float* __restrict__ w1v, const float* __restrict__ v1,
    const float* __restrict__ w3v, const float* __restrict__ v3)
{
    int j = blockIdx.x, e = blockIdx.y;
    const float* src = nullptr;
    if      (j < Rr)            src = w1v + ((size_t)e * Rr + j) * Hd;
    else if (j < R2)            src = v1  + ((size_t)e * Rr + j - Rr) * Hd;
    else if (j >= 320 && j < 320 + Rr) src = w3v + ((size_t)e * Rr + j - 320) * Hd;
    else if (j >= 320 + Rr && j < 320 + R2) src = v3 + ((size_t)e * Rr + j - 320 - Rr) * Hd;
    __half2* dst = (__half2*)(g_Bp + ((size_t)e * 640 + j) * Hd);
    for (int i = threadIdx.x; i < Hd / 2; i += 256) {
        float2 v = src ? ((const float2*)src)[i] : make_float2(0.f, 0.f);
        dst[i] = __floats2half2_rn(v.x, v.y);
    }
}

template <int SEL>  // 0: Bg(w1u,u1,I)  1: Bu(w3u,u3,I)  2: Bo(w2u,u2,H)
__global__ __launch_bounds__(320) void k_pack320(
    const float* __restrict__ W, const float* __restrict__ U)
{
    constexpr int ROWS = (SEL == 2) ? Hd : Id;
    __half* D = (SEL == 0) ? g_Bg : (SEL == 1) ? g_Bu : g_Bo;
    int e = blockIdx.y;
    int r = blockIdx.x * 4 + (threadIdx.x / 80);
    int c4 = (threadIdx.x % 80) * 4;
    const float* w = W + ((size_t)e * ROWS + r) * Rr;
    const float* u = U + ((size_t)e * ROWS + r) * Rr;
    float v[4];
#pragma unroll
    for (int j = 0; j < 4; j++) {
        int k = c4 + j;
        v[j] = (k < Rr) ? w[k] : ((k < R2) ? u[k - Rr] : 0.f);
    }
    __half2 h0 = __floats2half2_rn(v[0], v[1]);
    __half2 h1 = __floats2half2_rn(v[2], v[3]);
    uint2 pk = make_uint2(*(uint32_t*)&h0, *(uint32_t*)&h1);
    *(uint2*)(D + ((size_t)e * ROWS + r) * 320 + c4) = pk;
}

__global__ __launch_bounds__(256) void k_conv_Bq(
    const float* __restrict__ w2v, const float* __restrict__ v2)
{
    int j = blockIdx.x, e = blockIdx.y;   // j in [0,320)
    const float* src = nullptr;
    if      (j < Rr) src = w2v + ((size_t)e * Rr + j) * Id;
    else if (j < R2) src = v2  + ((size_t)e * Rr + j - Rr) * Id;
    __half2* dst = (__half2*)(g_Bq + ((size_t)e * 384 + j) * Id);
    for (int i = threadIdx.x; i < Id / 2; i += 256) {
        float2 v = src ? ((const float2*)src)[i] : make_float2(0.f, 0.f);
        dst[i] = __floats2half2_rn(v.x, v.y);
    }
}

// per-group qsum: rows [off[e0], end)
__global__ __launch_bounds__(256) void k_qsum_g(int e0) {
    int start = g_off[e0];
    int end   = (e0 + 4 < Ee) ? g_off[e0 + 4] : RT;
    int idx = blockIdx.x * 256 + threadIdx.x;
    int row = idx / 320;
    if (row >= end - start) return;
    size_t i = (size_t)(start + row) * 320 + (idx % 320);
    constexpr size_t S = (size_t)RT * 320;
    float s = g_Qf[i] + g_Qf[i + S] + g_Qf[i + 2 * S] + g_Qf[i + 3 * S];
    g_Qh[i] = __float2half_rn(s);
}

// ---------------- router (fused: logits fp32 + x -> fp16), 16 tokens/CTA ----------------
__device__ __forceinline__ float warpsum(float v) {
#pragma unroll
    for (int o = 16; o; o >>= 1) v += __shfl_down_sync(0xffffffffu, v, o);
    return v;
}

__global__ __launch_bounds__(256) void router_kernel(
    const float* __restrict__ x, const float* __restrict__ gw, float* __restrict__ logits)
{
    extern __shared__ float sgw[];   // [Ee * Hd] = 128KB
    int tid = threadIdx.x;
    for (int i = tid; i < Ee * Hd / 4; i += 256)
        ((float4*)sgw)[i] = ((const float4*)gw)[i];
    __syncthreads();

    int lane = tid & 31, grp = tid >> 5;
#pragma unroll
    for (int tt = 0; tt < 2; tt++) {
        int t = blockIdx.x * 16 + grp * 2 + tt;
        const float4* xr = (const float4*)(x + (size_t)t * Hd);
        __half2* dh = (__half2*)(g_xh + (size_t)t * Hd);

        float acc[Ee];
#pragma unroll
        for (int e = 0; e < Ee; e++) acc[e] = 0.f;

        for (int it = 0; it < Hd / 4 / 32; it++) {
            int i = lane + it * 32;
            float4 xv = xr[i];
            dh[2 * i]     = __floats2half2_rn(xv.x, xv.y);
            dh[2 * i + 1] = __floats2half2_rn(xv.z, xv.w);
#pragma unroll
            for (int e = 0; e < Ee; e++) {
                float4 wv = ((const float4*)(sgw + (size_t)e * Hd))[i];
                acc[e] = fmaf(xv.x, wv.x, fmaf(xv.y, wv.y, fmaf(xv.z, wv.z, fmaf(xv.w, wv.w, acc[e]))));
            }
        }
#pragma unroll
        for (int e = 0; e < Ee; e++) {
            float s = warpsum(acc[e]);
            if (lane == 0) logits[(size_t)t * Ee + e] = s;
        }
    }
}

__global__ void prep_kernel() { if (threadIdx.x < Ee) g_cnt[threadIdx.x] = 0; }

__global__ void route_kernel(const float* __restrict__ logits)
{
    int t = blockIdx.x * blockDim.x + threadIdx.x;
    if (t >= Tt) return;
    float l[Ee];
#pragma unroll
    for (int e = 0; e < Ee; e++) l[e] = logits[(size_t)t * Ee + e];
    int i1 = 0; float m1 = l[0];
#pragma unroll
    for (int e = 1; e < Ee; e++) if (l[e] > m1) { m1 = l[e]; i1 = e; }
    int i2 = -1; float m2 = -1e30f;
#pragma unroll
    for (int e = 0; e < Ee; e++) if (e != i1 && l[e] > m2) { m2 = l[e]; i2 = e; }
    float w1 = 1.f / (1.f + expf(m2 - m1));
    float w2 = 1.f - w1;
    int p = atomicAdd(&g_cnt[i1], 1); g_tok[i1][p] = t; g_wt[i1][p] = w1;
    p     = atomicAdd(&g_cnt[i2], 1); g_tok[i2][p] = t; g_wt[i2][p] = w2;
}

__global__ void offsets_kernel()
{
    if (threadIdx.x == 0) {
        int s = 0;
        for (int e = 0; e < Ee; e++) { g_off[e] = s; s += g_cnt[e]; }
    }
}

// ---------------- fp16 HMMA GEMM (128-M tile family, single-A), expert-group ----------------
// KIND 0: P = gather(xh) @ Bp^T       K=4096 NC=64  N=640(5)    3-stage
// KIND 1: h = silu(P@Bg^T)*(P@Bu^T)   fused NC=10 (gate 0-4, up 5-9), 2-stage + stash
// KIND 3: out += wt * (Q @ Bo^T)      K=320 NC=5    N=4096(32)  3-stage
template <int KIND>
__global__ __launch_bounds__(256, 2) void moe_mma(float* __restrict__ outp, int ebase)
{
    constexpr int NSTAGE = (KIND == 1) ? 2 : STAGES;
    constexpr int STAGE_B = 2 * TILE_B;
    constexpr int NCc   = (KIND == 0) ? 64 : (KIND == 1) ? 10 : 5;
    constexpr int Kb    = (KIND == 0) ? Hd : 320;
    constexpr int Brows = (KIND == 0) ? 640 : (KIND == 1) ? Id : Hd;

    int e     = ebase + blockIdx.z;
    int n_e   = g_cnt[e];
    int mbase = blockIdx.x * 128;
    if (mbase >= n_e) return;
    int nbase = blockIdx.y * 128;
    int off   = g_off[e];

    extern __shared__ char smem[];
    uint32_t smem_u32 = smem_to_u32(smem);
    __half2* sg2 = (__half2*)(smem + NSTAGE * STAGE_B);   // KIND1 silu stash (32KB, per-thread)

    int tid = threadIdx.x, lane = tid & 31, wid = tid >> 5;
    int wm = wid & 1, wn = wid >> 1;
    int row = tid >> 1, half = tid & 1;
    int ml = mbase + row;
    unsigned szA = (ml < n_e) ? 16u : 0u;

    const __half* Ah_row;
    if (KIND == 0) {
        int t = (ml < n_e) ? g_tok[e][ml] : 0;
        Ah_row = g_xh + (size_t)t * Hd;
    } else {
        size_t r = (size_t)off + ((ml < n_e) ? ml : 0);
        Ah_row = (KIND == 1) ? (g_Ph + r * 640) : (g_Qh + r * 320);
    }

    const __half *BrowG = nullptr, *BrowU = nullptr, *Brow = nullptr;
    if (KIND == 1) {
        size_t ro = ((size_t)e * Brows + nbase + row) * 320;
        BrowG = g_Bg + ro;
        BrowU = g_Bu + ro;
    } else {
        const __half* Bm = (KIND == 0) ? g_Bp : g_Bo;
        Brow = Bm + ((size_t)e * Brows + nbase + row) * Kb;
    }

    float acc[4][4][4];
#pragma unroll
    for (int i = 0; i < 4; i++)
#pragma unroll
        for (int j = 0; j < 4; j++)
#pragma unroll
            for (int q = 0; q < 4; q++) acc[i][j][q] = 0.f;

    auto issue_load = [&](int st, int c) {
        uint32_t sb = smem_u32 + st * STAGE_B;
        int acol = c * 64 + half * 32;
        const __half* bsrc;
        int bcol;
        if (KIND == 1) {
            bsrc = (c < 5) ? BrowG : BrowU;
            bcol = (c % 5) * 64 + half * 32;
        } else {
            bsrc = Brow;
            bcol = acol;
        }
#pragma unroll
        for (int i = 0; i < 4; i++) {
            uint32_t so = tile_off(row, half * 4 + i);
            CP16(sb + so, Ah_row + acol + i * 8, szA);
            CP16(sb + TILE_B + so, bsrc + bcol + i * 8, 16u);
        }
    };

    auto compute = [&](int st) {
        uint32_t base = smem_u32 + st * STAGE_B;
#pragma unroll
        for (int ks = 0; ks < 4; ks++) {
            uint32_t Ahf[4][4], Bf[4][2];
#pragma unroll
            for (int mf = 0; mf < 4; mf++) {
                int ar = wm * 64 + mf * 16 + (lane & 15);
                LDSM4(Ahf[mf], base + tile_off(ar, ks * 2 + (lane >> 4)));
            }
#pragma unroll
            for (int g = 0; g < 2; g++) {
                int br = wn * 32 + g * 16 + ((lane >> 4) << 3) + (lane & 7);
                uint32_t o = tile_off(br, ks * 2 + ((lane >> 3) & 1));
                uint32_t r[4];
                LDSM4(r, base + TILE_B + o);
                Bf[2 * g][0] = r[0]; Bf[2 * g][1] = r[1];
                Bf[2 * g + 1][0] = r[2]; Bf[2 * g + 1][1] = r[3];
            }
#pragma unroll
            for (int mf = 0; mf < 4; mf++)
#pragma unroll
                for (int nf = 0; nf < 4; nf++) MMA16816(acc[mf][nf], Ahf[mf], Bf[nf]);
        }
    };

    auto stash_silu = [&]() {
#pragma unroll
        for (int mf = 0; mf < 4; mf++)
#pragma unroll
            for (int nf = 0; nf < 4; nf++)
#pragma unroll
                for (int qp = 0; qp < 2; qp++) {
                    float g0 = acc[mf][nf][qp * 2 + 0];
                    float g1 = acc[mf][nf][qp * 2 + 1];
                    g0 = g0 / (1.f + __expf(-g0));
                    g1 = g1 / (1.f + __expf(-g1));
                    sg2[((mf * 4 + nf) * 2 + qp) * 256 + tid] = __floats2half2_rn(g0, g1);
                    acc[mf][nf][qp * 2 + 0] = 0.f;
                    acc[mf][nf][qp * 2 + 1] = 0.f;
                }
    };

    if (NSTAGE == 3) {
        issue_load(0, 0); CP_COMMIT();
        if (NCc > 1) issue_load(1, 1);
        CP_COMMIT();
        CP_WAIT(1);
        __syncthreads();
        for (int c = 0; c < NCc; c++) {
            if (c + 2 < NCc) issue_load((c + 2) % 3, c + 2);
            CP_COMMIT();
            compute(c % 3);
            CP_WAIT(1);
            __syncthreads();
        }
    } else {
        issue_load(0, 0); CP_COMMIT();
        CP_WAIT(0);
        __syncthreads();
        for (int c = 0; c < NCc; c++) {
            if (c + 1 < NCc) { issue_load((c + 1) & 1, c + 1); CP_COMMIT(); }
            compute(c & 1);
            if (KIND == 1 && c == 4) stash_silu();   // per-thread smem, no sync needed
            if (c + 1 < NCc) { CP_WAIT(0); __syncthreads(); }
        }
    }

    // epilogue
#pragma unroll
    for (int mf = 0; mf < 4; mf++)
#pragma unroll
        for (int nf = 0; nf < 4; nf++)
#pragma unroll
            for (int qp = 0; qp < 2; qp++) {
                int r = wm * 64 + mf * 16 + (lane >> 2) + qp * 8;
                int m = mbase + r;
                if (m >= n_e) continue;
                int col = nbase + wn * 32 + nf * 8 + (lane & 3) * 2;
                float v0 = acc[mf][nf][qp * 2 + 0];
                float v1 = acc[mf][nf][qp * 2 + 1];
                if (KIND == 0) {
                    size_t b = (size_t)(off + m) * 640 + col;
                    *(__half2*)(g_Ph + b) = __floats2half2_rn(v0, v1);
                } else if (KIND == 1) {
                    float2 sf = __half22float2(sg2[((mf * 4 + nf) * 2 + qp) * 256 + tid]);
                    v0 *= sf.x;
                    v1 *= sf.y;
                    size_t b = (size_t)(off + m) * Id + col;
                    *(__half2*)(g_hh + b) = __floats2half2_rn(v0, v1);
                } else {
                    float wt  = g_wt[e][m];
                    int   tok = g_tok[e][m];
                    float* dst = outp + (size_t)tok * Hd + col;
                    atomicAdd(dst, wt * v0);
                    atomicAdd(dst + 1, wt * v1);
                }
            }
}

// ---------------- Q GEMM: M=64 x N=160, 4 K-slices, 3-stage, 2 CTAs/SM ----------------
#define QA_B 8192
#define QB_B 20480
#define QST_B (QA_B + QB_B)   // 28672
__global__ __launch_bounds__(256, 2) void moe_mma_q(int ebase)
{
    int e     = ebase + blockIdx.z;
    int n_e   = g_cnt[e];
    int mbase = blockIdx.x * 64;
    if (mbase >= n_e) return;
    int nhalf  = blockIdx.y & 1;
    int kslice = blockIdx.y >> 1;
    int cbase  = kslice * QNC;
    int off    = g_off[e];

    extern __shared__ char smem[];
    uint32_t smem_u32 = smem_to_u32(smem);

    int tid = threadIdx.x, lane = tid & 31, wid = tid >> 5;
    int wm = wid >> 2, wn = wid & 3;   // 2M x 4N warps

    float acc[2][5][4];
#pragma unroll
    for (int i = 0; i < 2; i++)
#pragma unroll
        for (int j = 0; j < 5; j++)
#pragma unroll
            for (int q = 0; q < 4; q++) acc[i][j][q] = 0.f;

    const __half* Bq_e = g_Bq + (size_t)e * 384 * Id + (size_t)(nhalf * 160) * Id;

    auto issue_load = [&](int st, int c) {
        uint32_t sb = smem_u32 + st * QST_B;
        int col = (cbase + c) * 64;
#pragma unroll
        for (int i = 0; i < 7; i++) {
            int ci = tid + i * 256;
            if (ci < 512) {
                int row = ci >> 3, ch = ci & 7;
                int m = mbase + row;
                unsigned sz = (m < n_e) ? 16u : 0u;
                const __half* src = g_hh + ((size_t)off + ((m < n_e) ? m : 0)) * Id + col + ch * 8;
                CP16(sb + tile_off(row, ch), src, sz);
            } else {
                int bi = ci - 512;   // < 1280
                int row = bi >> 3, ch = bi & 7;
                const __half* src = Bq_e + (size_t)row * Id + col + ch * 8;
                CP16(sb + QA_B + tile_off(row, ch), src, 16u);
            }
        }
    };

    auto compute = [&](int st) {
        uint32_t base = smem_u32 + st * QST_B;
#pragma unroll
        for (int ks = 0; ks < 4; ks++) {
            uint32_t Af[2][4], Bf[5][2];
#pragma unroll
            for (int mf = 0; mf < 2; mf++) {
                int ar = wm * 32 + mf * 16 + (lane & 15);
                LDSM4(Af[mf], base + tile_off(ar, ks * 2 + (lane >> 4)));
            }
#pragma unroll
            for (int g = 0; g < 2; g++) {
                int br = wn * 40 + g * 16 + ((lane >> 4) << 3) + (lane & 7);
                uint32_t o = tile_off(br, ks * 2 + ((lane >> 3) & 1));
                uint32_t r[4];
                LDSM4(r, base + QA_B + o);
                Bf[2 * g][0] = r[0]; Bf[2 * g][1] = r[1];
                Bf[2 * g + 1][0] = r[2]; Bf[2 * g + 1][1] = r[3];
            }
            {
                int br = wn * 40 + 32 + (lane & 7);
                uint32_t o = tile_off(br, ks * 2 + ((lane >> 3) & 1));
                uint32_t r2[2];
                LDSM2(r2, base + QA_B + o);
                Bf[4][0] = r2[0]; Bf[4][1] = r2[1];
            }
#pragma unroll
            for (int mf = 0; mf < 2; mf++)
#pragma unroll
                for (int nf = 0; nf < 5; nf++) MMA16816(acc[mf][nf], Af[mf], Bf[nf]);
        }
    };

    issue_load(0, 0); CP_COMMIT();
    issue_load(1, 1); CP_COMMIT();
    CP_WAIT(1);
    __syncthreads();

    for (int c = 0; c < QNC; c++) {
        if (c + 2 < QNC) issue_load((c + 2) % 3, c + 2);
        CP_COMMIT();
        compute(c % 3);
        CP_WAIT(1);
        __syncthreads();
    }

    float* qf = g_Qf + (size_t)kslice * RT * 320;
#pragma unroll
    for (int mf = 0; mf < 2; mf++)
#pragma unroll
        for (int nf = 0; nf < 5; nf++)
#pragma unroll
            for (int qp = 0; qp < 2; qp++) {
                int m = mbase + wm * 32 + mf * 16 + (lane >> 2) + qp * 8;
                if (m >= n_e) continue;
                int col = nhalf * 160 + wn * 40 + nf * 8 + (lane & 3) * 2;
                size_t b = (size_t)(off + m) * 320 + col;
                qf[b]     = acc[mf][nf][qp * 2 + 0];
                qf[b + 1] = acc[mf][nf][qp * 2 + 1];
            }
}

// ---------------- launch ----------------
extern "C" void kernel_launch(void* const* d_in, const int* in_sizes, int n_in,
                              void* d_out, int out_size)
{
    const float* x    = (const float*)d_in[0];
    const float* gw   = (const float*)d_in[1];
    const float* w1u  = (const float*)d_in[2];
    const float* w1v  = (const float*)d_in[3];
    const float* w2u  = (const float*)d_in[4];
    const float* w2v  = (const float*)d_in[5];
    const float* w3u  = (const float*)d_in[6];
    const float* w3v  = (const float*)d_in[7];
    const float* u1   = (const float*)d_in[8];
    const float* v1   = (const float*)d_in[9];
    const float* u2   = (const float*)d_in[10];
    const float* v2   = (const float*)d_in[11];
    const float* u3   = (const float*)d_in[12];
    const float* v3   = (const float*)d_in[13];

    float* outp   = (float*)d_out;
    float* logits = outp + (size_t)Tt * Hd;

    static cudaStream_t s_pack = nullptr;
    static cudaEvent_t evStart, evBp, evBgu, evBq, evBo, evRoute, evZero, evDoneB;
    if (!s_pack) {
        cudaStreamCreateWithFlags(&s_pack, cudaStreamNonBlocking);
        cudaEventCreateWithFlags(&evStart, cudaEventDisableTiming);
        cudaEventCreateWithFlags(&evBp,    cudaEventDisableTiming);
        cudaEventCreateWithFlags(&evBgu,   cudaEventDisableTiming);
        cudaEventCreateWithFlags(&evBq,    cudaEventDisableTiming);
        cudaEventCreateWithFlags(&evBo,    cudaEventDisableTiming);
        cudaEventCreateWithFlags(&evRoute, cudaEventDisableTiming);
        cudaEventCreateWithFlags(&evZero,  cudaEventDisableTiming);
        cudaEventCreateWithFlags(&evDoneB, cudaEventDisableTiming);

        int smem_s2 = STAGES * 2 * TILE_B;        // 96KB (KIND0/3)
        int smem_gu = 2 * 2 * TILE_B + 32768;     // 96KB (KIND1)
        int smem_q  = 3 * QST_B;                  // 84KB
        cudaFuncSetAttribute(moe_mma<0>, cudaFuncAttributeMaxDynamicSharedMemorySize, smem_s2);
        cudaFuncSetAttribute(moe_mma<1>, cudaFuncAttributeMaxDynamicSharedMemorySize, smem_gu);
        cudaFuncSetAttribute(moe_mma<3>, cudaFuncAttributeMaxDynamicSharedMemorySize, smem_s2);
        cudaFuncSetAttribute(moe_mma_q,  cudaFuncAttributeMaxDynamicSharedMemorySize, smem_q);
        cudaFuncSetAttribute(router_kernel, cudaFuncAttributeMaxDynamicSharedMemorySize,
                             Ee * Hd * (int)sizeof(float));   // 128KB
    }
    int smem_s2 = STAGES * 2 * TILE_B;
    int smem_gu = 2 * 2 * TILE_B + 32768;
    int smem_q  = 3 * QST_B;

    // fork: weight packing on side stream
    cudaEventRecord(evStart, 0);
    cudaStreamWaitEvent(s_pack, evStart, 0);

    k_conv_Bp<<<dim3(640, Ee), 256, 0, s_pack>>>(w1v, v1, w3v, v3);
    cudaEventRecord(evBp, s_pack);
    k_pack320<0><<<dim3(Id / 4, Ee), 320, 0, s_pack>>>(w1u, u1);
    k_pack320<1><<<dim3(Id / 4, Ee), 320, 0, s_pack>>>(w3u, u3);
    cudaEventRecord(evBgu, s_pack);
    k_conv_Bq<<<dim3(320, Ee), 256, 0, s_pack>>>(w2v, v2);
    cudaEventRecord(evBq, s_pack);
    k_pack320<2><<<dim3(Hd / 4, Ee), 320, 0, s_pack>>>(w2u, u2);
    cudaEventRecord(evBo, s_pack);

    // main stream: routing chain (router also produces g_xh)
    cudaMemsetAsync(outp, 0, (size_t)Tt * Hd * sizeof(float));
    cudaEventRecord(evZero, 0);
    prep_kernel<<<1, 32>>>();
    router_kernel<<<Tt / 16, 256, Ee * Hd * sizeof(float)>>>(x, gw, logits);
    route_kernel<<<Tt / 256, 256>>>(logits);
    offsets_kernel<<<1, 32>>>();
    cudaEventRecord(evRoute, 0);

    // group A (experts 0-3) on main stream
    cudaStreamWaitEvent(0, evBp, 0);
    moe_mma<0><<<dim3(32, 5, 4), 256, smem_s2>>>(nullptr, 0);
    cudaStreamWaitEvent(0, evBgu, 0);
    moe_mma<1><<<dim3(32, 112, 4), 256, smem_gu>>>(nullptr, 0);
    cudaStreamWaitEvent(0, evBq, 0);
    moe_mma_q<<<dim3(64, 2 * QSPLIT, 4), 256, smem_q>>>(0);
    k_qsum_g<<<(RT * 320) / 256, 256>>>(0);
    cudaStreamWaitEvent(0, evBo, 0);
    moe_mma<3><<<dim3(32, 32, 4), 256, smem_s2>>>(outp, 0);

    // group B (experts 4-7) on s_pack (packing already ordered there)
    cudaStreamWaitEvent(s_pack, evRoute, 0);
    cudaStreamWaitEvent(s_pack, evZero, 0);
    moe_mma<0><<<dim3(32, 5, 4), 256, smem_s2, s_pack>>>(nullptr, 4);
    moe_mma<1><<<dim3(32, 112, 4), 256, smem_gu, s_pack>>>(nullptr, 4);
    moe_mma_q<<<dim3(64, 2 * QSPLIT, 4), 256, smem_q, s_pack>>>(4);
    k_qsum_g<<<(RT * 320) / 256, 256, 0, s_pack>>>(4);
    cudaStreamWaitEvent(s_pack, evBo, 0);
    moe_mma<3><<<dim3(32, 32, 4), 256, smem_s2, s_pack>>>(outp, 4);
    cudaEventRecord(evDoneB, s_pack);

    // join
    cudaStreamWaitEvent(0, evDoneB, 0);
}